// round 8
// baseline (speedup 1.0000x reference)
#include <cuda_runtime.h>
#include <cuda_bf16.h>
#include <math.h>
#include <stdint.h>

// Problem shape (fixed)
#define BB 8
#define LL 2048
#define DD 1024
#define NH 16
#define HD 64
#define MTOK (BB * LL)        // 16384 tokens
#define KTOT (3 * DD)         // 3072: A=[hi|lo|hi], B=[hi|hi|lo]

// ======================= scratch ============================================
__device__ float        g_QKV[(size_t)MTOK * KTOT];    // 192 MB (q|k|v per row)
__device__ __nv_bfloat16 g_Aexp[(size_t)MTOK * KTOT];  // 96 MB
__device__ __nv_bfloat16 g_Wexp[4ULL * DD * KTOT];     // 24 MB (q,k,v,o)
__device__ float        g_bqkv[KTOT];

// ======================= small helpers ======================================
__device__ __forceinline__ uint32_t smem_u32(const void* p) {
    uint32_t a;
    asm("{ .reg .u64 t; cvta.to.shared.u64 t, %1; cvt.u32.u64 %0, t; }"
        : "=r"(a) : "l"(p));
    return a;
}
__device__ __forceinline__ void cp_async16(uint32_t dst, const void* src) {
    asm volatile("cp.async.cg.shared.global [%0], [%1], 16;" :: "r"(dst), "l"(src));
}
#define CP_COMMIT() asm volatile("cp.async.commit_group;" ::: "memory")

__device__ __forceinline__ void ldsm_x4(uint32_t* r, uint32_t addr) {
    asm volatile("ldmatrix.sync.aligned.m8n8.x4.shared.b16 {%0,%1,%2,%3}, [%4];"
                 : "=r"(r[0]), "=r"(r[1]), "=r"(r[2]), "=r"(r[3]) : "r"(addr));
}
__device__ __forceinline__ void mma16816(float* c, const uint32_t* a,
                                         uint32_t b0, uint32_t b1) {
    asm volatile(
        "mma.sync.aligned.m16n8k16.row.col.f32.bf16.bf16.f32 "
        "{%0,%1,%2,%3}, {%4,%5,%6,%7}, {%8,%9}, {%0,%1,%2,%3};"
        : "+f"(c[0]), "+f"(c[1]), "+f"(c[2]), "+f"(c[3])
        : "r"(a[0]), "r"(a[1]), "r"(a[2]), "r"(a[3]), "r"(b0), "r"(b1));
}

// ======================= conversion kernels =================================
// x [M, DD] fp32 -> Aexp [M, KTOT] bf16: [hi | lo | hi]
__global__ void __launch_bounds__(256) convert_Aexp_kernel(
    const float* __restrict__ in, __nv_bfloat16* __restrict__ out)
{
    int i = blockIdx.x * blockDim.x + threadIdx.x;
    if (i >= MTOK * DD / 4) return;
    int row = i >> 8;
    int col = (i & 255) * 4;
    float4 v = reinterpret_cast<const float4*>(in)[i];
    __nv_bfloat16 h0 = __float2bfloat16_rn(v.x);
    __nv_bfloat16 h1 = __float2bfloat16_rn(v.y);
    __nv_bfloat16 h2 = __float2bfloat16_rn(v.z);
    __nv_bfloat16 h3 = __float2bfloat16_rn(v.w);
    __nv_bfloat16 l0 = __float2bfloat16_rn(v.x - __bfloat162float(h0));
    __nv_bfloat16 l1 = __float2bfloat16_rn(v.y - __bfloat162float(h1));
    __nv_bfloat16 l2 = __float2bfloat16_rn(v.z - __bfloat162float(h2));
    __nv_bfloat16 l3 = __float2bfloat16_rn(v.w - __bfloat162float(h3));
    __nv_bfloat162 ph0 = __halves2bfloat162(h0, h1);
    __nv_bfloat162 ph1 = __halves2bfloat162(h2, h3);
    __nv_bfloat162 pl0 = __halves2bfloat162(l0, l1);
    __nv_bfloat162 pl1 = __halves2bfloat162(l2, l3);
    uint2 uh, ul;
    uh.x = *reinterpret_cast<uint32_t*>(&ph0);
    uh.y = *reinterpret_cast<uint32_t*>(&ph1);
    ul.x = *reinterpret_cast<uint32_t*>(&pl0);
    ul.y = *reinterpret_cast<uint32_t*>(&pl1);
    size_t base = (size_t)row * KTOT;
    *reinterpret_cast<uint2*>(out + base + col) = uh;
    *reinterpret_cast<uint2*>(out + base + DD + col) = ul;
    *reinterpret_cast<uint2*>(out + base + 2 * DD + col) = uh;
}

// W [K=DD, N=DD] fp32 -> T [N, KTOT] bf16: [hi | hi | lo] along K (transposed)
__global__ void __launch_bounds__(256) convert_Wexp_kernel(
    const float* __restrict__ W, __nv_bfloat16* __restrict__ T)
{
    __shared__ float t[32][33];
    int bx = blockIdx.x * 32, by = blockIdx.y * 32;
    int tx = threadIdx.x, ty = threadIdx.y;
    for (int j = ty; j < 32; j += 8)
        t[j][tx] = W[(size_t)(by + j) * DD + bx + tx];
    __syncthreads();
    for (int j = ty; j < 32; j += 8) {
        float v = t[tx][j];
        __nv_bfloat16 h = __float2bfloat16_rn(v);
        __nv_bfloat16 l = __float2bfloat16_rn(v - __bfloat162float(h));
        size_t o = (size_t)(bx + j) * KTOT + by + tx;
        T[o] = h; T[o + DD] = h; T[o + 2 * DD] = l;
    }
}

__global__ void pack_bias_kernel(const float* __restrict__ bq,
                                 const float* __restrict__ bk,
                                 const float* __restrict__ bv,
                                 float* __restrict__ out)
{
    int i = blockIdx.x * blockDim.x + threadIdx.x;
    if (i >= KTOT) return;
    out[i] = (i < DD) ? bq[i] : (i < 2 * DD) ? bk[i - DD] : bv[i - 2 * DD];
}

// ======================= mma.sync GEMM ======================================
// C[M,N] = A[M,KTOT] @ B[N,KTOT]^T + bias
// CTA tile 128x128, 8 warps (4x2), warp tile 32x64, BK=32, 5 stages.
#define GBM 128
#define GBN 128
#define GBK 32
#define GSTAGES 5
#define APAD 8
#define SROW (GBK + APAD)                    // 40 bf16 = 80 B
#define TILE_BYTES (GBM * SROW * 2)          // 10240
#define STAGE_BYTES (2 * TILE_BYTES)         // 20480 (A + B)
#define GEMM_SMEM (GSTAGES * STAGE_BYTES)    // 102400
#define GNIT (KTOT / GBK)                    // 96

__global__ void __launch_bounds__(256) gemm_mma_kernel(
    const __nv_bfloat16* __restrict__ A, const __nv_bfloat16* __restrict__ B,
    const float* __restrict__ bias, float* __restrict__ C, int N)
{
    extern __shared__ __nv_bfloat16 sm[];
    const uint32_t sbase = smem_u32(sm);

    const int tid = threadIdx.x;
    const int lane = tid & 31;
    const int wid = tid >> 5;
    const int wm = wid & 3;          // 0..3 -> 32-row slice
    const int wn = wid >> 2;         // 0..1 -> 64-col slice
    const int bm = blockIdx.y * GBM;
    const int bn = blockIdx.x * GBN;

    float acc[2][8][4];
#pragma unroll
    for (int i = 0; i < 2; i++)
#pragma unroll
        for (int j = 0; j < 8; j++)
#pragma unroll
            for (int q = 0; q < 4; q++) acc[i][j][q] = 0.f;

    // stage loader: A and B each 512 chunks of 16B, 2 per thread
    auto load_stage = [&](int it, int s) {
        const int kt = it * GBK;
        const uint32_t st = sbase + s * STAGE_BYTES;
#pragma unroll
        for (int i = 0; i < 2; i++) {
            int c = tid + 256 * i;
            int r = c >> 2, ch = c & 3;
            uint32_t off = (r * SROW + ch * 8) * 2;
            cp_async16(st + off,              A + (size_t)(bm + r) * KTOT + kt + ch * 8);
            cp_async16(st + TILE_BYTES + off, B + (size_t)(bn + r) * KTOT + kt + ch * 8);
        }
        CP_COMMIT();
    };

    load_stage(0, 0);
    load_stage(1, 1);
    load_stage(2, 2);
    load_stage(3, 3);

    const int a_row = wm * 32 + (lane & 15);
    const int a_kof = ((lane >> 4) & 1) * 8;
    const int b_row = wn * 64 + ((lane >> 4) & 1) * 8 + (lane & 7);
    const int b_kof = ((lane >> 3) & 1) * 8;

    uint32_t af[2][2][4], bf[2][4][4];

    auto load_frags = [&](int buf, uint32_t abase, uint32_t bbase, int k0) {
#pragma unroll
        for (int mi = 0; mi < 2; mi++)
            ldsm_x4(af[buf][mi], abase + ((a_row + mi * 16) * SROW + k0 + a_kof) * 2);
#pragma unroll
        for (int nj = 0; nj < 4; nj++)
            ldsm_x4(bf[buf][nj], bbase + ((b_row + nj * 16) * SROW + k0 + b_kof) * 2);
    };
    auto do_mmas = [&](int buf) {
#pragma unroll
        for (int mi = 0; mi < 2; mi++)
#pragma unroll
            for (int nj = 0; nj < 4; nj++) {
                mma16816(acc[mi][2 * nj],     af[buf][mi], bf[buf][nj][0], bf[buf][nj][1]);
                mma16816(acc[mi][2 * nj + 1], af[buf][mi], bf[buf][nj][2], bf[buf][nj][3]);
            }
    };

    int s = 0;          // stage of iter it
    int sp = 4;         // stage of iter it+4
    for (int it = 0; it < GNIT; it++) {
        asm volatile("cp.async.wait_group 3;" ::: "memory");
        __syncthreads();

        if (it + 4 < GNIT) load_stage(it + 4, sp);
        else CP_COMMIT();

        const uint32_t abase = sbase + s * STAGE_BYTES;
        const uint32_t bbase = abase + TILE_BYTES;
        load_frags(0, abase, bbase, 0);
        load_frags(1, abase, bbase, 16);   // in flight under buf-0 MMAs
        do_mmas(0);
        do_mmas(1);

        if (++s == GSTAGES) s = 0;
        if (++sp == GSTAGES) sp = 0;
    }

    // epilogue
#pragma unroll
    for (int mi = 0; mi < 2; mi++) {
#pragma unroll
        for (int ni = 0; ni < 8; ni++) {
            int row = bm + wm * 32 + mi * 16 + (lane >> 2);
            int col = bn + wn * 64 + ni * 8 + (lane & 3) * 2;
            float b0 = __ldg(&bias[col]), b1 = __ldg(&bias[col + 1]);
            float2 v0 = {acc[mi][ni][0] + b0, acc[mi][ni][1] + b1};
            float2 v1 = {acc[mi][ni][2] + b0, acc[mi][ni][3] + b1};
            *reinterpret_cast<float2*>(&C[(size_t)row * N + col]) = v0;
            *reinterpret_cast<float2*>(&C[(size_t)(row + 8) * N + col]) = v1;
        }
    }
}

// ======================= per-token attention ================================
// 2 tokens per 128-thread block. QKV row = [q(1024)|k(1024)|v(1024)].
// Online softmax + recompute: no per-thread score array (low register count).
// Output written directly as bf16 [hi|lo|hi] expansion into Aexp.
__global__ void __launch_bounds__(128) attn_kernel(
    const float* __restrict__ QKV, __nv_bfloat16* __restrict__ Aexp)
{
    __shared__ float sk[2][DD];
    __shared__ float sv[2][DD];

    const int tid = threadIdx.x;
    const int sub = tid >> 6;        // token within block
    const int i = tid & 63;          // my HD row
    const int t = blockIdx.x * 2 + sub;
    const float* row = QKV + (size_t)t * KTOT;

#pragma unroll
    for (int h = 0; h < 4; h++) {
        int idx = i + h * 64;
        reinterpret_cast<float4*>(sk[sub])[idx] =
            reinterpret_cast<const float4*>(row + DD)[idx];
        reinterpret_cast<float4*>(sv[sub])[idx] =
            reinterpret_cast<const float4*>(row + 2 * DD)[idx];
    }
    float4 q0 = reinterpret_cast<const float4*>(row)[i * 4 + 0];
    float4 q1 = reinterpret_cast<const float4*>(row)[i * 4 + 1];
    float4 q2 = reinterpret_cast<const float4*>(row)[i * 4 + 2];
    float4 q3 = reinterpret_cast<const float4*>(row)[i * 4 + 3];
    __syncthreads();

    // score for key kk (fp32, identical both passes)
    auto score = [&](int kk) -> float {
        float4 k0 = reinterpret_cast<const float4*>(sk[sub])[kk * 4 + 0];
        float4 k1 = reinterpret_cast<const float4*>(sk[sub])[kk * 4 + 1];
        float4 k2 = reinterpret_cast<const float4*>(sk[sub])[kk * 4 + 2];
        float4 k3 = reinterpret_cast<const float4*>(sk[sub])[kk * 4 + 3];
        float dot = q0.x * k0.x + q0.y * k0.y + q0.z * k0.z + q0.w * k0.w
                  + q1.x * k1.x + q1.y * k1.y + q1.z * k1.z + q1.w * k1.w
                  + q2.x * k2.x + q2.y * k2.y + q2.z * k2.z + q2.w * k2.w
                  + q3.x * k3.x + q3.y * k3.y + q3.z * k3.z + q3.w * k3.w;
        return dot * 0.25f + 1e-6f;
    };

    // pass 1: online max + sum (only kk <= i can be valid)
    float mx = -INFINITY, sum = 0.f;
    for (int kk = 0; kk <= i; kk++) {
        float v = score(kk);
        bool valid = (v != 0.0f);
        float vv = valid ? v : -INFINITY;
        if (vv > mx) {                 // first valid hit also lands here
            sum = sum * __expf(mx - vv) + 1.f;   // exp(-inf)=0 on first hit
            mx = vv;
        } else if (valid) {
            sum += __expf(vv - mx);
        }
    }
    float inv = 1.f / sum;

    // pass 2: recompute probs, accumulate PV
    float4 acc0 = {0, 0, 0, 0}, acc1 = {0, 0, 0, 0};
    float4 acc2 = {0, 0, 0, 0}, acc3 = {0, 0, 0, 0};
    for (int kk = 0; kk <= i; kk++) {
        float v = score(kk);
        float p = (v != 0.0f) ? __expf(v - mx) * inv : 0.f;
        float4 v0 = reinterpret_cast<const float4*>(sv[sub])[kk * 4 + 0];
        float4 v1 = reinterpret_cast<const float4*>(sv[sub])[kk * 4 + 1];
        float4 v2 = reinterpret_cast<const float4*>(sv[sub])[kk * 4 + 2];
        float4 v3 = reinterpret_cast<const float4*>(sv[sub])[kk * 4 + 3];
        acc0.x = fmaf(p, v0.x, acc0.x); acc0.y = fmaf(p, v0.y, acc0.y);
        acc0.z = fmaf(p, v0.z, acc0.z); acc0.w = fmaf(p, v0.w, acc0.w);
        acc1.x = fmaf(p, v1.x, acc1.x); acc1.y = fmaf(p, v1.y, acc1.y);
        acc1.z = fmaf(p, v1.z, acc1.z); acc1.w = fmaf(p, v1.w, acc1.w);
        acc2.x = fmaf(p, v2.x, acc2.x); acc2.y = fmaf(p, v2.y, acc2.y);
        acc2.z = fmaf(p, v2.z, acc2.z); acc2.w = fmaf(p, v2.w, acc2.w);
        acc3.x = fmaf(p, v3.x, acc3.x); acc3.y = fmaf(p, v3.y, acc3.y);
        acc3.z = fmaf(p, v3.z, acc3.z); acc3.w = fmaf(p, v3.w, acc3.w);
    }

    // split + expanded store
    float a[16] = {acc0.x, acc0.y, acc0.z, acc0.w, acc1.x, acc1.y, acc1.z, acc1.w,
                   acc2.x, acc2.y, acc2.z, acc2.w, acc3.x, acc3.y, acc3.z, acc3.w};
    uint32_t hi[8], lo[8];
#pragma unroll
    for (int j = 0; j < 8; j++) {
        __nv_bfloat16 h0 = __float2bfloat16_rn(a[2 * j]);
        __nv_bfloat16 h1 = __float2bfloat16_rn(a[2 * j + 1]);
        __nv_bfloat16 l0 = __float2bfloat16_rn(a[2 * j] - __bfloat162float(h0));
        __nv_bfloat16 l1 = __float2bfloat16_rn(a[2 * j + 1] - __bfloat162float(h1));
        __nv_bfloat162 ph = __halves2bfloat162(h0, h1);
        __nv_bfloat162 pl = __halves2bfloat162(l0, l1);
        hi[j] = *reinterpret_cast<uint32_t*>(&ph);
        lo[j] = *reinterpret_cast<uint32_t*>(&pl);
    }
    __nv_bfloat16* ob = Aexp + (size_t)t * KTOT + i * NH;
    uint4* u = reinterpret_cast<uint4*>(hi);
    reinterpret_cast<uint4*>(ob)[0] = u[0];
    reinterpret_cast<uint4*>(ob)[1] = u[1];
    reinterpret_cast<uint4*>(ob + 2 * DD)[0] = u[0];
    reinterpret_cast<uint4*>(ob + 2 * DD)[1] = u[1];
    uint4* ul = reinterpret_cast<uint4*>(lo);
    reinterpret_cast<uint4*>(ob + DD)[0] = ul[0];
    reinterpret_cast<uint4*>(ob + DD)[1] = ul[1];
}

// ======================= launch =============================================
extern "C" void kernel_launch(void* const* d_in, const int* in_sizes, int n_in,
                              void* d_out, int out_size)
{
    const float* x  = (const float*)d_in[0];
    const float* Wq = (const float*)d_in[1];
    const float* bq = (const float*)d_in[2];
    const float* Wk = (const float*)d_in[3];
    const float* bk = (const float*)d_in[4];
    const float* Wv = (const float*)d_in[5];
    const float* bv = (const float*)d_in[6];
    const float* Wo = (const float*)d_in[7];
    const float* bo = (const float*)d_in[8];
    float* out = (float*)d_out;

    float *QKVp, *bqkv;
    __nv_bfloat16 *Aexp, *Wexp;
    cudaGetSymbolAddress((void**)&QKVp, g_QKV);
    cudaGetSymbolAddress((void**)&Aexp, g_Aexp);
    cudaGetSymbolAddress((void**)&Wexp, g_Wexp);
    cudaGetSymbolAddress((void**)&bqkv, g_bqkv);

    cudaFuncSetAttribute(gemm_mma_kernel,
                         cudaFuncAttributeMaxDynamicSharedMemorySize, GEMM_SMEM);

    const int n4 = MTOK * DD / 4;
    dim3 cgrid((n4 + 255) / 256);
    dim3 wgrid(DD / 32, DD / 32), wblk(32, 8);

    pack_bias_kernel<<<(KTOT + 255) / 256, 256>>>(bq, bk, bv, bqkv);       // 0
    convert_Aexp_kernel<<<cgrid, 256>>>(x, Aexp);                          // 1
    convert_Wexp_kernel<<<wgrid, wblk>>>(Wq, Wexp + 0ULL * DD * KTOT);     // 2
    convert_Wexp_kernel<<<wgrid, wblk>>>(Wk, Wexp + 1ULL * DD * KTOT);     // 3
    convert_Wexp_kernel<<<wgrid, wblk>>>(Wv, Wexp + 2ULL * DD * KTOT);     // 4

    // fused QKV projection: C = Aexp @ [Wq|Wk|Wv]^T  (N = 3072)
    dim3 qkv_grid(KTOT / GBN, MTOK / GBM);   // (24, 128)
    gemm_mma_kernel<<<qkv_grid, 256, GEMM_SMEM>>>(Aexp, Wexp, bqkv, QKVp, KTOT);  // 5

    attn_kernel<<<MTOK / 2, 128>>>(QKVp, Aexp);                            // 6

    convert_Wexp_kernel<<<wgrid, wblk>>>(Wo, Wexp + 3ULL * DD * KTOT);     // 7

    dim3 o_grid(DD / GBN, MTOK / GBM);       // (8, 128)
    gemm_mma_kernel<<<o_grid, 256, GEMM_SMEM>>>(Aexp, Wexp + 3ULL * DD * KTOT, bo, out, DD);  // 8
}

// round 9
// speedup vs baseline: 1.1154x; 1.1154x over previous
#include <cuda_runtime.h>
#include <cuda_bf16.h>
#include <math.h>
#include <stdint.h>

// Problem shape (fixed)
#define BB 8
#define LL 2048
#define DD 1024
#define NH 16
#define HD 64
#define MTOK (BB * LL)        // 16384 tokens
#define KTOT (3 * DD)         // 3072: A=[hi|lo|hi], B=[hi|hi|lo]

// ======================= scratch ============================================
__device__ float        g_QKV[(size_t)MTOK * KTOT];    // 192 MB (q|k|v per row)
__device__ __nv_bfloat16 g_Aexp[(size_t)MTOK * KTOT];  // 96 MB
__device__ __nv_bfloat16 g_Wexp[4ULL * DD * KTOT];     // 24 MB (q,k,v,o)
__device__ float        g_bqkv[KTOT];

// ======================= small helpers ======================================
__device__ __forceinline__ uint32_t smem_u32(const void* p) {
    uint32_t a;
    asm("{ .reg .u64 t; cvta.to.shared.u64 t, %1; cvt.u32.u64 %0, t; }"
        : "=r"(a) : "l"(p));
    return a;
}
__device__ __forceinline__ void cp_async16(uint32_t dst, const void* src) {
    asm volatile("cp.async.cg.shared.global [%0], [%1], 16;" :: "r"(dst), "l"(src));
}
#define CP_COMMIT() asm volatile("cp.async.commit_group;" ::: "memory")

__device__ __forceinline__ void ldsm_x4(uint32_t* r, uint32_t addr) {
    asm volatile("ldmatrix.sync.aligned.m8n8.x4.shared.b16 {%0,%1,%2,%3}, [%4];"
                 : "=r"(r[0]), "=r"(r[1]), "=r"(r[2]), "=r"(r[3]) : "r"(addr));
}
__device__ __forceinline__ void mma16816(float* c, const uint32_t* a,
                                         uint32_t b0, uint32_t b1) {
    asm volatile(
        "mma.sync.aligned.m16n8k16.row.col.f32.bf16.bf16.f32 "
        "{%0,%1,%2,%3}, {%4,%5,%6,%7}, {%8,%9}, {%0,%1,%2,%3};"
        : "+f"(c[0]), "+f"(c[1]), "+f"(c[2]), "+f"(c[3])
        : "r"(a[0]), "r"(a[1]), "r"(a[2]), "r"(a[3]), "r"(b0), "r"(b1));
}

// ======================= conversion kernels =================================
// x [M, DD] fp32 -> Aexp [M, KTOT] bf16: [hi | lo | hi]
__global__ void __launch_bounds__(256) convert_Aexp_kernel(
    const float* __restrict__ in, __nv_bfloat16* __restrict__ out)
{
    int i = blockIdx.x * blockDim.x + threadIdx.x;
    if (i >= MTOK * DD / 4) return;
    int row = i >> 8;
    int col = (i & 255) * 4;
    float4 v = reinterpret_cast<const float4*>(in)[i];
    __nv_bfloat16 h0 = __float2bfloat16_rn(v.x);
    __nv_bfloat16 h1 = __float2bfloat16_rn(v.y);
    __nv_bfloat16 h2 = __float2bfloat16_rn(v.z);
    __nv_bfloat16 h3 = __float2bfloat16_rn(v.w);
    __nv_bfloat16 l0 = __float2bfloat16_rn(v.x - __bfloat162float(h0));
    __nv_bfloat16 l1 = __float2bfloat16_rn(v.y - __bfloat162float(h1));
    __nv_bfloat16 l2 = __float2bfloat16_rn(v.z - __bfloat162float(h2));
    __nv_bfloat16 l3 = __float2bfloat16_rn(v.w - __bfloat162float(h3));
    __nv_bfloat162 ph0 = __halves2bfloat162(h0, h1);
    __nv_bfloat162 ph1 = __halves2bfloat162(h2, h3);
    __nv_bfloat162 pl0 = __halves2bfloat162(l0, l1);
    __nv_bfloat162 pl1 = __halves2bfloat162(l2, l3);
    uint2 uh, ul;
    uh.x = *reinterpret_cast<uint32_t*>(&ph0);
    uh.y = *reinterpret_cast<uint32_t*>(&ph1);
    ul.x = *reinterpret_cast<uint32_t*>(&pl0);
    ul.y = *reinterpret_cast<uint32_t*>(&pl1);
    size_t base = (size_t)row * KTOT;
    *reinterpret_cast<uint2*>(out + base + col) = uh;
    *reinterpret_cast<uint2*>(out + base + DD + col) = ul;
    *reinterpret_cast<uint2*>(out + base + 2 * DD + col) = uh;
}

// W [K=DD, N=DD] fp32 -> T [N, KTOT] bf16: [hi | hi | lo] along K (transposed)
__global__ void __launch_bounds__(256) convert_Wexp_kernel(
    const float* __restrict__ W, __nv_bfloat16* __restrict__ T)
{
    __shared__ float t[32][33];
    int bx = blockIdx.x * 32, by = blockIdx.y * 32;
    int tx = threadIdx.x, ty = threadIdx.y;
    for (int j = ty; j < 32; j += 8)
        t[j][tx] = W[(size_t)(by + j) * DD + bx + tx];
    __syncthreads();
    for (int j = ty; j < 32; j += 8) {
        float v = t[tx][j];
        __nv_bfloat16 h = __float2bfloat16_rn(v);
        __nv_bfloat16 l = __float2bfloat16_rn(v - __bfloat162float(h));
        size_t o = (size_t)(bx + j) * KTOT + by + tx;
        T[o] = h; T[o + DD] = h; T[o + 2 * DD] = l;
    }
}

__global__ void pack_bias_kernel(const float* __restrict__ bq,
                                 const float* __restrict__ bk,
                                 const float* __restrict__ bv,
                                 float* __restrict__ out)
{
    int i = blockIdx.x * blockDim.x + threadIdx.x;
    if (i >= KTOT) return;
    out[i] = (i < DD) ? bq[i] : (i < 2 * DD) ? bk[i - DD] : bv[i - 2 * DD];
}

// ======================= mma.sync GEMM ======================================
// C[M,N] = A[M,KTOT] @ B[N,KTOT]^T + bias
// CTA tile 128x128, 8 warps (4x2), warp tile 32x64, BK=64, 3 stages.
#define GBM 128
#define GBN 128
#define GBK 64
#define GSTAGES 3
#define APAD 8
#define SROW (GBK + APAD)                    // 72 bf16 = 144 B
#define TILE_BYTES (GBM * SROW * 2)          // 18432
#define STAGE_BYTES (2 * TILE_BYTES)         // 36864 (A + B)
#define GEMM_SMEM (GSTAGES * STAGE_BYTES)    // 110592
#define GNIT (KTOT / GBK)                    // 48

__global__ void __launch_bounds__(256, 2) gemm_mma_kernel(
    const __nv_bfloat16* __restrict__ A, const __nv_bfloat16* __restrict__ B,
    const float* __restrict__ bias, float* __restrict__ C, int N)
{
    extern __shared__ __nv_bfloat16 sm[];
    const uint32_t sbase = smem_u32(sm);

    const int tid = threadIdx.x;
    const int lane = tid & 31;
    const int wid = tid >> 5;
    const int wm = wid & 3;          // 0..3 -> 32-row slice
    const int wn = wid >> 2;         // 0..1 -> 64-col slice
    const int bm = blockIdx.y * GBM;
    const int bn = blockIdx.x * GBN;

    float acc[2][8][4];
#pragma unroll
    for (int i = 0; i < 2; i++)
#pragma unroll
        for (int j = 0; j < 8; j++)
#pragma unroll
            for (int q = 0; q < 4; q++) acc[i][j][q] = 0.f;

    // stage loader: A and B each 1024 chunks of 16B, 4 per thread
    auto load_stage = [&](int it, int s) {
        const int kt = it * GBK;
        const uint32_t st = sbase + s * STAGE_BYTES;
#pragma unroll
        for (int i = 0; i < 4; i++) {
            int c = tid + 256 * i;
            int r = c >> 3, ch = c & 7;
            uint32_t off = (r * SROW + ch * 8) * 2;
            cp_async16(st + off,              A + (size_t)(bm + r) * KTOT + kt + ch * 8);
            cp_async16(st + TILE_BYTES + off, B + (size_t)(bn + r) * KTOT + kt + ch * 8);
        }
        CP_COMMIT();
    };

    load_stage(0, 0);
    load_stage(1, 1);

    const int a_row = wm * 32 + (lane & 15);
    const int a_kof = ((lane >> 4) & 1) * 8;
    const int b_row = wn * 64 + ((lane >> 4) & 1) * 8 + (lane & 7);
    const int b_kof = ((lane >> 3) & 1) * 8;

    uint32_t af[2][2][4], bf[2][4][4];

    auto load_frags = [&](int buf, uint32_t abase, uint32_t bbase, int k0) {
#pragma unroll
        for (int mi = 0; mi < 2; mi++)
            ldsm_x4(af[buf][mi], abase + ((a_row + mi * 16) * SROW + k0 + a_kof) * 2);
#pragma unroll
        for (int nj = 0; nj < 4; nj++)
            ldsm_x4(bf[buf][nj], bbase + ((b_row + nj * 16) * SROW + k0 + b_kof) * 2);
    };
    auto do_mmas = [&](int buf) {
#pragma unroll
        for (int mi = 0; mi < 2; mi++)
#pragma unroll
            for (int nj = 0; nj < 4; nj++) {
                mma16816(acc[mi][2 * nj],     af[buf][mi], bf[buf][nj][0], bf[buf][nj][1]);
                mma16816(acc[mi][2 * nj + 1], af[buf][mi], bf[buf][nj][2], bf[buf][nj][3]);
            }
    };

    for (int it = 0; it < GNIT; it++) {
        const int s = it % 3;
        asm volatile("cp.async.wait_group 1;" ::: "memory");
        __syncthreads();

        if (it + 2 < GNIT) load_stage(it + 2, (it + 2) % 3);
        else CP_COMMIT();

        const uint32_t abase = sbase + s * STAGE_BYTES;
        const uint32_t bbase = abase + TILE_BYTES;
        // 4 k16 steps, fragments double-buffered so LDSM flies under MMA
        load_frags(0, abase, bbase, 0);
#pragma unroll
        for (int ks = 0; ks < 4; ks++) {
            if (ks < 3) load_frags((ks + 1) & 1, abase, bbase, (ks + 1) * 16);
            do_mmas(ks & 1);
        }
    }

    // epilogue
#pragma unroll
    for (int mi = 0; mi < 2; mi++) {
#pragma unroll
        for (int ni = 0; ni < 8; ni++) {
            int row = bm + wm * 32 + mi * 16 + (lane >> 2);
            int col = bn + wn * 64 + ni * 8 + (lane & 3) * 2;
            float b0 = __ldg(&bias[col]), b1 = __ldg(&bias[col + 1]);
            float2 v0 = {acc[mi][ni][0] + b0, acc[mi][ni][1] + b1};
            float2 v1 = {acc[mi][ni][2] + b0, acc[mi][ni][3] + b1};
            *reinterpret_cast<float2*>(&C[(size_t)row * N + col]) = v0;
            *reinterpret_cast<float2*>(&C[(size_t)(row + 8) * N + col]) = v1;
        }
    }
}

// ======================= per-token attention (R7 version) ===================
// 2 tokens per 128-thread block. QKV row = [q(1024)|k(1024)|v(1024)].
// Output written directly as bf16 [hi|lo|hi] expansion into Aexp.
__global__ void __launch_bounds__(128) attn_kernel(
    const float* __restrict__ QKV, __nv_bfloat16* __restrict__ Aexp)
{
    __shared__ float sk[2][DD];
    __shared__ float sv[2][DD];

    const int tid = threadIdx.x;
    const int sub = tid >> 6;        // token within block
    const int i = tid & 63;          // my HD row
    const int t = blockIdx.x * 2 + sub;
    const float* row = QKV + (size_t)t * KTOT;

#pragma unroll
    for (int h = 0; h < 4; h++) {
        int idx = i + h * 64;
        reinterpret_cast<float4*>(sk[sub])[idx] =
            reinterpret_cast<const float4*>(row + DD)[idx];
        reinterpret_cast<float4*>(sv[sub])[idx] =
            reinterpret_cast<const float4*>(row + 2 * DD)[idx];
    }
    float4 q0 = reinterpret_cast<const float4*>(row)[i * 4 + 0];
    float4 q1 = reinterpret_cast<const float4*>(row)[i * 4 + 1];
    float4 q2 = reinterpret_cast<const float4*>(row)[i * 4 + 2];
    float4 q3 = reinterpret_cast<const float4*>(row)[i * 4 + 3];
    __syncthreads();

    float s[HD];
    float mx = -INFINITY;
#pragma unroll 8
    for (int kk = 0; kk < HD; kk++) {
        float4 k0 = reinterpret_cast<const float4*>(sk[sub])[kk * 4 + 0];
        float4 k1 = reinterpret_cast<const float4*>(sk[sub])[kk * 4 + 1];
        float4 k2 = reinterpret_cast<const float4*>(sk[sub])[kk * 4 + 2];
        float4 k3 = reinterpret_cast<const float4*>(sk[sub])[kk * 4 + 3];
        float dot = q0.x * k0.x + q0.y * k0.y + q0.z * k0.z + q0.w * k0.w
                  + q1.x * k1.x + q1.y * k1.y + q1.z * k1.z + q1.w * k1.w
                  + q2.x * k2.x + q2.y * k2.y + q2.z * k2.z + q2.w * k2.w
                  + q3.x * k3.x + q3.y * k3.y + q3.z * k3.z + q3.w * k3.w;
        float val = dot * 0.25f + 1e-6f;
        bool valid = (kk <= i) && (val != 0.0f);
        s[kk] = valid ? val : -INFINITY;
        if (valid) mx = fmaxf(mx, val);
    }

    float sum = 0.f;
#pragma unroll 8
    for (int kk = 0; kk < HD; kk++) {
        float e = (s[kk] == -INFINITY) ? 0.f : __expf(s[kk] - mx);
        s[kk] = e;
        sum += e;
    }
    float inv = 1.f / sum;

    float4 acc0 = {0, 0, 0, 0}, acc1 = {0, 0, 0, 0};
    float4 acc2 = {0, 0, 0, 0}, acc3 = {0, 0, 0, 0};
#pragma unroll 8
    for (int kk = 0; kk < HD; kk++) {    // uniform: masked probs are exactly 0
        float p = s[kk] * inv;
        float4 v0 = reinterpret_cast<const float4*>(sv[sub])[kk * 4 + 0];
        float4 v1 = reinterpret_cast<const float4*>(sv[sub])[kk * 4 + 1];
        float4 v2 = reinterpret_cast<const float4*>(sv[sub])[kk * 4 + 2];
        float4 v3 = reinterpret_cast<const float4*>(sv[sub])[kk * 4 + 3];
        acc0.x = fmaf(p, v0.x, acc0.x); acc0.y = fmaf(p, v0.y, acc0.y);
        acc0.z = fmaf(p, v0.z, acc0.z); acc0.w = fmaf(p, v0.w, acc0.w);
        acc1.x = fmaf(p, v1.x, acc1.x); acc1.y = fmaf(p, v1.y, acc1.y);
        acc1.z = fmaf(p, v1.z, acc1.z); acc1.w = fmaf(p, v1.w, acc1.w);
        acc2.x = fmaf(p, v2.x, acc2.x); acc2.y = fmaf(p, v2.y, acc2.y);
        acc2.z = fmaf(p, v2.z, acc2.z); acc2.w = fmaf(p, v2.w, acc2.w);
        acc3.x = fmaf(p, v3.x, acc3.x); acc3.y = fmaf(p, v3.y, acc3.y);
        acc3.z = fmaf(p, v3.z, acc3.z); acc3.w = fmaf(p, v3.w, acc3.w);
    }

    // split + expanded store
    float a[16] = {acc0.x, acc0.y, acc0.z, acc0.w, acc1.x, acc1.y, acc1.z, acc1.w,
                   acc2.x, acc2.y, acc2.z, acc2.w, acc3.x, acc3.y, acc3.z, acc3.w};
    uint32_t hi[8], lo[8];
#pragma unroll
    for (int j = 0; j < 8; j++) {
        __nv_bfloat16 h0 = __float2bfloat16_rn(a[2 * j]);
        __nv_bfloat16 h1 = __float2bfloat16_rn(a[2 * j + 1]);
        __nv_bfloat16 l0 = __float2bfloat16_rn(a[2 * j] - __bfloat162float(h0));
        __nv_bfloat16 l1 = __float2bfloat16_rn(a[2 * j + 1] - __bfloat162float(h1));
        __nv_bfloat162 ph = __halves2bfloat162(h0, h1);
        __nv_bfloat162 pl = __halves2bfloat162(l0, l1);
        hi[j] = *reinterpret_cast<uint32_t*>(&ph);
        lo[j] = *reinterpret_cast<uint32_t*>(&pl);
    }
    __nv_bfloat16* ob = Aexp + (size_t)t * KTOT + i * NH;
    uint4* u = reinterpret_cast<uint4*>(hi);
    reinterpret_cast<uint4*>(ob)[0] = u[0];
    reinterpret_cast<uint4*>(ob)[1] = u[1];
    reinterpret_cast<uint4*>(ob + 2 * DD)[0] = u[0];
    reinterpret_cast<uint4*>(ob + 2 * DD)[1] = u[1];
    uint4* ul = reinterpret_cast<uint4*>(lo);
    reinterpret_cast<uint4*>(ob + DD)[0] = ul[0];
    reinterpret_cast<uint4*>(ob + DD)[1] = ul[1];
}

// ======================= launch =============================================
extern "C" void kernel_launch(void* const* d_in, const int* in_sizes, int n_in,
                              void* d_out, int out_size)
{
    const float* x  = (const float*)d_in[0];
    const float* Wq = (const float*)d_in[1];
    const float* bq = (const float*)d_in[2];
    const float* Wk = (const float*)d_in[3];
    const float* bk = (const float*)d_in[4];
    const float* Wv = (const float*)d_in[5];
    const float* bv = (const float*)d_in[6];
    const float* Wo = (const float*)d_in[7];
    const float* bo = (const float*)d_in[8];
    float* out = (float*)d_out;

    float *QKVp, *bqkv;
    __nv_bfloat16 *Aexp, *Wexp;
    cudaGetSymbolAddress((void**)&QKVp, g_QKV);
    cudaGetSymbolAddress((void**)&Aexp, g_Aexp);
    cudaGetSymbolAddress((void**)&Wexp, g_Wexp);
    cudaGetSymbolAddress((void**)&bqkv, g_bqkv);

    cudaFuncSetAttribute(gemm_mma_kernel,
                         cudaFuncAttributeMaxDynamicSharedMemorySize, GEMM_SMEM);

    const int n4 = MTOK * DD / 4;
    dim3 cgrid((n4 + 255) / 256);
    dim3 wgrid(DD / 32, DD / 32), wblk(32, 8);

    pack_bias_kernel<<<(KTOT + 255) / 256, 256>>>(bq, bk, bv, bqkv);       // 0
    convert_Aexp_kernel<<<cgrid, 256>>>(x, Aexp);                          // 1
    convert_Wexp_kernel<<<wgrid, wblk>>>(Wq, Wexp + 0ULL * DD * KTOT);     // 2
    convert_Wexp_kernel<<<wgrid, wblk>>>(Wk, Wexp + 1ULL * DD * KTOT);     // 3
    convert_Wexp_kernel<<<wgrid, wblk>>>(Wv, Wexp + 2ULL * DD * KTOT);     // 4

    // fused QKV projection: C = Aexp @ [Wq|Wk|Wv]^T  (N = 3072)
    dim3 qkv_grid(KTOT / GBN, MTOK / GBM);   // (24, 128)
    gemm_mma_kernel<<<qkv_grid, 256, GEMM_SMEM>>>(Aexp, Wexp, bqkv, QKVp, KTOT);  // 5

    attn_kernel<<<MTOK / 2, 128>>>(QKVp, Aexp);                            // 6

    convert_Wexp_kernel<<<wgrid, wblk>>>(Wo, Wexp + 3ULL * DD * KTOT);     // 7

    dim3 o_grid(DD / GBN, MTOK / GBM);       // (8, 128)
    gemm_mma_kernel<<<o_grid, 256, GEMM_SMEM>>>(Aexp, Wexp + 3ULL * DD * KTOT, bo, out, DD);  // 8
}

// round 10
// speedup vs baseline: 1.5467x; 1.3867x over previous
#include <cuda_runtime.h>
#include <cuda_fp16.h>
#include <math.h>
#include <stdint.h>

// Problem shape (fixed)
#define BB 8
#define LL 2048
#define DD 1024
#define NH 16
#define HD 64
#define MTOK (BB * LL)        // 16384 tokens
#define KEXP (2 * DD)         // 2048: A=[hi|lo] fp16, B=[hi|hi] fp16
#define NQKV (3 * DD)         // 3072: fused q|k|v output width

// ======================= scratch ============================================
__device__ float  g_QKV[(size_t)MTOK * NQKV];     // 192 MB (q|k|v per row)
__device__ __half g_Aexp[(size_t)MTOK * KEXP];    // 64 MB
__device__ __half g_Wexp[4ULL * DD * KEXP];       // 16 MB (q,k,v,o)
__device__ float  g_bqkv[NQKV];

// ======================= small helpers ======================================
__device__ __forceinline__ uint32_t smem_u32(const void* p) {
    uint32_t a;
    asm("{ .reg .u64 t; cvta.to.shared.u64 t, %1; cvt.u32.u64 %0, t; }"
        : "=r"(a) : "l"(p));
    return a;
}
__device__ __forceinline__ void cp_async16(uint32_t dst, const void* src) {
    asm volatile("cp.async.cg.shared.global [%0], [%1], 16;" :: "r"(dst), "l"(src));
}
#define CP_COMMIT() asm volatile("cp.async.commit_group;" ::: "memory")

__device__ __forceinline__ void ldsm_x4(uint32_t* r, uint32_t addr) {
    asm volatile("ldmatrix.sync.aligned.m8n8.x4.shared.b16 {%0,%1,%2,%3}, [%4];"
                 : "=r"(r[0]), "=r"(r[1]), "=r"(r[2]), "=r"(r[3]) : "r"(addr));
}
__device__ __forceinline__ void mma16816(float* c, const uint32_t* a,
                                         uint32_t b0, uint32_t b1) {
    asm volatile(
        "mma.sync.aligned.m16n8k16.row.col.f32.f16.f16.f32 "
        "{%0,%1,%2,%3}, {%4,%5,%6,%7}, {%8,%9}, {%0,%1,%2,%3};"
        : "+f"(c[0]), "+f"(c[1]), "+f"(c[2]), "+f"(c[3])
        : "r"(a[0]), "r"(a[1]), "r"(a[2]), "r"(a[3]), "r"(b0), "r"(b1));
}

// ======================= conversion kernels =================================
// x [M, DD] fp32 -> Aexp [M, KEXP] fp16: [hi | lo]  (hi = RN(x), lo = RN(x-hi))
__global__ void __launch_bounds__(256) convert_Aexp_kernel(
    const float* __restrict__ in, __half* __restrict__ out)
{
    int i = blockIdx.x * blockDim.x + threadIdx.x;
    if (i >= MTOK * DD / 4) return;
    int row = i >> 8;
    int col = (i & 255) * 4;
    float4 v = reinterpret_cast<const float4*>(in)[i];
    __half h0 = __float2half_rn(v.x);
    __half h1 = __float2half_rn(v.y);
    __half h2 = __float2half_rn(v.z);
    __half h3 = __float2half_rn(v.w);
    __half l0 = __float2half_rn(v.x - __half2float(h0));
    __half l1 = __float2half_rn(v.y - __half2float(h1));
    __half l2 = __float2half_rn(v.z - __half2float(h2));
    __half l3 = __float2half_rn(v.w - __half2float(h3));
    __half2 ph0 = __halves2half2(h0, h1);
    __half2 ph1 = __halves2half2(h2, h3);
    __half2 pl0 = __halves2half2(l0, l1);
    __half2 pl1 = __halves2half2(l2, l3);
    uint2 uh, ul;
    uh.x = *reinterpret_cast<uint32_t*>(&ph0);
    uh.y = *reinterpret_cast<uint32_t*>(&ph1);
    ul.x = *reinterpret_cast<uint32_t*>(&pl0);
    ul.y = *reinterpret_cast<uint32_t*>(&pl1);
    size_t base = (size_t)row * KEXP;
    *reinterpret_cast<uint2*>(out + base + col) = uh;
    *reinterpret_cast<uint2*>(out + base + DD + col) = ul;
}

// W [K=DD, N=DD] fp32 -> T [N, KEXP] fp16: [hi | hi] along K (transposed)
__global__ void __launch_bounds__(256) convert_Wexp_kernel(
    const float* __restrict__ W, __half* __restrict__ T)
{
    __shared__ float t[32][33];
    int bx = blockIdx.x * 32, by = blockIdx.y * 32;
    int tx = threadIdx.x, ty = threadIdx.y;
    for (int j = ty; j < 32; j += 8)
        t[j][tx] = W[(size_t)(by + j) * DD + bx + tx];
    __syncthreads();
    for (int j = ty; j < 32; j += 8) {
        float v = t[tx][j];
        __half h = __float2half_rn(v);
        size_t o = (size_t)(bx + j) * KEXP + by + tx;
        T[o] = h; T[o + DD] = h;
    }
}

__global__ void pack_bias_kernel(const float* __restrict__ bq,
                                 const float* __restrict__ bk,
                                 const float* __restrict__ bv,
                                 float* __restrict__ out)
{
    int i = blockIdx.x * blockDim.x + threadIdx.x;
    if (i >= NQKV) return;
    out[i] = (i < DD) ? bq[i] : (i < 2 * DD) ? bk[i - DD] : bv[i - 2 * DD];
}

// ======================= mma.sync GEMM ======================================
// C[M,N] = A[M,KEXP] @ B[N,KEXP]^T + bias
// CTA tile 128x128, 8 warps (4x2), warp tile 32x64, BK=64, 3 stages.
#define GBM 128
#define GBN 128
#define GBK 64
#define GSTAGES 3
#define APAD 8
#define SROW (GBK + APAD)                    // 72 fp16 = 144 B
#define TILE_BYTES (GBM * SROW * 2)          // 18432
#define STAGE_BYTES (2 * TILE_BYTES)         // 36864 (A + B)
#define GEMM_SMEM (GSTAGES * STAGE_BYTES)    // 110592
#define GNIT (KEXP / GBK)                    // 32

__global__ void __launch_bounds__(256, 2) gemm_mma_kernel(
    const __half* __restrict__ A, const __half* __restrict__ B,
    const float* __restrict__ bias, float* __restrict__ C, int N)
{
    extern __shared__ __half sm[];
    const uint32_t sbase = smem_u32(sm);

    const int tid = threadIdx.x;
    const int lane = tid & 31;
    const int wid = tid >> 5;
    const int wm = wid & 3;          // 0..3 -> 32-row slice
    const int wn = wid >> 2;         // 0..1 -> 64-col slice
    const int bm = blockIdx.y * GBM;
    const int bn = blockIdx.x * GBN;

    float acc[2][8][4];
#pragma unroll
    for (int i = 0; i < 2; i++)
#pragma unroll
        for (int j = 0; j < 8; j++)
#pragma unroll
            for (int q = 0; q < 4; q++) acc[i][j][q] = 0.f;

    // stage loader: A and B each 1024 chunks of 16B, 4 per thread
    auto load_stage = [&](int it, int s) {
        const int kt = it * GBK;
        const uint32_t st = sbase + s * STAGE_BYTES;
#pragma unroll
        for (int i = 0; i < 4; i++) {
            int c = tid + 256 * i;
            int r = c >> 3, ch = c & 7;
            uint32_t off = (r * SROW + ch * 8) * 2;
            cp_async16(st + off,              A + (size_t)(bm + r) * KEXP + kt + ch * 8);
            cp_async16(st + TILE_BYTES + off, B + (size_t)(bn + r) * KEXP + kt + ch * 8);
        }
        CP_COMMIT();
    };

    load_stage(0, 0);
    load_stage(1, 1);

    const int a_row = wm * 32 + (lane & 15);
    const int a_kof = ((lane >> 4) & 1) * 8;
    const int b_row = wn * 64 + ((lane >> 4) & 1) * 8 + (lane & 7);
    const int b_kof = ((lane >> 3) & 1) * 8;

    uint32_t af[2][2][4], bf[2][4][4];

    auto load_frags = [&](int buf, uint32_t abase, uint32_t bbase, int k0) {
#pragma unroll
        for (int mi = 0; mi < 2; mi++)
            ldsm_x4(af[buf][mi], abase + ((a_row + mi * 16) * SROW + k0 + a_kof) * 2);
#pragma unroll
        for (int nj = 0; nj < 4; nj++)
            ldsm_x4(bf[buf][nj], bbase + ((b_row + nj * 16) * SROW + k0 + b_kof) * 2);
    };
    auto do_mmas = [&](int buf) {
#pragma unroll
        for (int mi = 0; mi < 2; mi++)
#pragma unroll
            for (int nj = 0; nj < 4; nj++) {
                mma16816(acc[mi][2 * nj],     af[buf][mi], bf[buf][nj][0], bf[buf][nj][1]);
                mma16816(acc[mi][2 * nj + 1], af[buf][mi], bf[buf][nj][2], bf[buf][nj][3]);
            }
    };

    for (int it = 0; it < GNIT; it++) {
        const int s = it % 3;
        asm volatile("cp.async.wait_group 1;" ::: "memory");
        __syncthreads();

        if (it + 2 < GNIT) load_stage(it + 2, (it + 2) % 3);
        else CP_COMMIT();

        const uint32_t abase = sbase + s * STAGE_BYTES;
        const uint32_t bbase = abase + TILE_BYTES;
        // 4 k16 steps, fragments double-buffered so LDSM flies under MMA
        load_frags(0, abase, bbase, 0);
#pragma unroll
        for (int ks = 0; ks < 4; ks++) {
            if (ks < 3) load_frags((ks + 1) & 1, abase, bbase, (ks + 1) * 16);
            do_mmas(ks & 1);
        }
    }

    // epilogue
#pragma unroll
    for (int mi = 0; mi < 2; mi++) {
#pragma unroll
        for (int ni = 0; ni < 8; ni++) {
            int row = bm + wm * 32 + mi * 16 + (lane >> 2);
            int col = bn + wn * 64 + ni * 8 + (lane & 3) * 2;
            float b0 = __ldg(&bias[col]), b1 = __ldg(&bias[col + 1]);
            float2 v0 = {acc[mi][ni][0] + b0, acc[mi][ni][1] + b1};
            float2 v1 = {acc[mi][ni][2] + b0, acc[mi][ni][3] + b1};
            *reinterpret_cast<float2*>(&C[(size_t)row * N + col]) = v0;
            *reinterpret_cast<float2*>(&C[(size_t)(row + 8) * N + col]) = v1;
        }
    }
}

// ======================= per-token attention ================================
// 2 tokens per 128-thread block. QKV row = [q(1024)|k(1024)|v(1024)].
// Output written directly as fp16 [hi|lo] split into Aexp.
__global__ void __launch_bounds__(128) attn_kernel(
    const float* __restrict__ QKV, __half* __restrict__ Aexp)
{
    __shared__ float sk[2][DD];
    __shared__ float sv[2][DD];

    const int tid = threadIdx.x;
    const int sub = tid >> 6;        // token within block
    const int i = tid & 63;          // my HD row
    const int t = blockIdx.x * 2 + sub;
    const float* row = QKV + (size_t)t * NQKV;

#pragma unroll
    for (int h = 0; h < 4; h++) {
        int idx = i + h * 64;
        reinterpret_cast<float4*>(sk[sub])[idx] =
            reinterpret_cast<const float4*>(row + DD)[idx];
        reinterpret_cast<float4*>(sv[sub])[idx] =
            reinterpret_cast<const float4*>(row + 2 * DD)[idx];
    }
    float4 q0 = reinterpret_cast<const float4*>(row)[i * 4 + 0];
    float4 q1 = reinterpret_cast<const float4*>(row)[i * 4 + 1];
    float4 q2 = reinterpret_cast<const float4*>(row)[i * 4 + 2];
    float4 q3 = reinterpret_cast<const float4*>(row)[i * 4 + 3];
    __syncthreads();

    float s[HD];
    float mx = -INFINITY;
#pragma unroll 8
    for (int kk = 0; kk < HD; kk++) {
        float4 k0 = reinterpret_cast<const float4*>(sk[sub])[kk * 4 + 0];
        float4 k1 = reinterpret_cast<const float4*>(sk[sub])[kk * 4 + 1];
        float4 k2 = reinterpret_cast<const float4*>(sk[sub])[kk * 4 + 2];
        float4 k3 = reinterpret_cast<const float4*>(sk[sub])[kk * 4 + 3];
        float dot = q0.x * k0.x + q0.y * k0.y + q0.z * k0.z + q0.w * k0.w
                  + q1.x * k1.x + q1.y * k1.y + q1.z * k1.z + q1.w * k1.w
                  + q2.x * k2.x + q2.y * k2.y + q2.z * k2.z + q2.w * k2.w
                  + q3.x * k3.x + q3.y * k3.y + q3.z * k3.z + q3.w * k3.w;
        float val = dot * 0.25f + 1e-6f;
        bool valid = (kk <= i) && (val != 0.0f);
        s[kk] = valid ? val : -INFINITY;
        if (valid) mx = fmaxf(mx, val);
    }

    float sum = 0.f;
#pragma unroll 8
    for (int kk = 0; kk < HD; kk++) {
        float e = (s[kk] == -INFINITY) ? 0.f : __expf(s[kk] - mx);
        s[kk] = e;
        sum += e;
    }
    float inv = 1.f / sum;

    float4 acc0 = {0, 0, 0, 0}, acc1 = {0, 0, 0, 0};
    float4 acc2 = {0, 0, 0, 0}, acc3 = {0, 0, 0, 0};
#pragma unroll 8
    for (int kk = 0; kk < HD; kk++) {    // uniform: masked probs are exactly 0
        float p = s[kk] * inv;
        float4 v0 = reinterpret_cast<const float4*>(sv[sub])[kk * 4 + 0];
        float4 v1 = reinterpret_cast<const float4*>(sv[sub])[kk * 4 + 1];
        float4 v2 = reinterpret_cast<const float4*>(sv[sub])[kk * 4 + 2];
        float4 v3 = reinterpret_cast<const float4*>(sv[sub])[kk * 4 + 3];
        acc0.x = fmaf(p, v0.x, acc0.x); acc0.y = fmaf(p, v0.y, acc0.y);
        acc0.z = fmaf(p, v0.z, acc0.z); acc0.w = fmaf(p, v0.w, acc0.w);
        acc1.x = fmaf(p, v1.x, acc1.x); acc1.y = fmaf(p, v1.y, acc1.y);
        acc1.z = fmaf(p, v1.z, acc1.z); acc1.w = fmaf(p, v1.w, acc1.w);
        acc2.x = fmaf(p, v2.x, acc2.x); acc2.y = fmaf(p, v2.y, acc2.y);
        acc2.z = fmaf(p, v2.z, acc2.z); acc2.w = fmaf(p, v2.w, acc2.w);
        acc3.x = fmaf(p, v3.x, acc3.x); acc3.y = fmaf(p, v3.y, acc3.y);
        acc3.z = fmaf(p, v3.z, acc3.z); acc3.w = fmaf(p, v3.w, acc3.w);
    }

    // fp16 split + store [hi | lo]
    float a[16] = {acc0.x, acc0.y, acc0.z, acc0.w, acc1.x, acc1.y, acc1.z, acc1.w,
                   acc2.x, acc2.y, acc2.z, acc2.w, acc3.x, acc3.y, acc3.z, acc3.w};
    uint32_t hi[8], lo[8];
#pragma unroll
    for (int j = 0; j < 8; j++) {
        __half h0 = __float2half_rn(a[2 * j]);
        __half h1 = __float2half_rn(a[2 * j + 1]);
        __half l0 = __float2half_rn(a[2 * j] - __half2float(h0));
        __half l1 = __float2half_rn(a[2 * j + 1] - __half2float(h1));
        __half2 ph = __halves2half2(h0, h1);
        __half2 pl = __halves2half2(l0, l1);
        hi[j] = *reinterpret_cast<uint32_t*>(&ph);
        lo[j] = *reinterpret_cast<uint32_t*>(&pl);
    }
    __half* ob = Aexp + (size_t)t * KEXP + i * NH;
    uint4* u = reinterpret_cast<uint4*>(hi);
    reinterpret_cast<uint4*>(ob)[0] = u[0];
    reinterpret_cast<uint4*>(ob)[1] = u[1];
    uint4* ul = reinterpret_cast<uint4*>(lo);
    reinterpret_cast<uint4*>(ob + DD)[0] = ul[0];
    reinterpret_cast<uint4*>(ob + DD)[1] = ul[1];
}

// ======================= launch =============================================
extern "C" void kernel_launch(void* const* d_in, const int* in_sizes, int n_in,
                              void* d_out, int out_size)
{
    const float* x  = (const float*)d_in[0];
    const float* Wq = (const float*)d_in[1];
    const float* bq = (const float*)d_in[2];
    const float* Wk = (const float*)d_in[3];
    const float* bk = (const float*)d_in[4];
    const float* Wv = (const float*)d_in[5];
    const float* bv = (const float*)d_in[6];
    const float* Wo = (const float*)d_in[7];
    const float* bo = (const float*)d_in[8];
    float* out = (float*)d_out;

    float *QKVp, *bqkv;
    __half *Aexp, *Wexp;
    cudaGetSymbolAddress((void**)&QKVp, g_QKV);
    cudaGetSymbolAddress((void**)&Aexp, g_Aexp);
    cudaGetSymbolAddress((void**)&Wexp, g_Wexp);
    cudaGetSymbolAddress((void**)&bqkv, g_bqkv);

    cudaFuncSetAttribute(gemm_mma_kernel,
                         cudaFuncAttributeMaxDynamicSharedMemorySize, GEMM_SMEM);

    const int n4 = MTOK * DD / 4;
    dim3 cgrid((n4 + 255) / 256);
    dim3 wgrid(DD / 32, DD / 32), wblk(32, 8);

    pack_bias_kernel<<<(NQKV + 255) / 256, 256>>>(bq, bk, bv, bqkv);       // 0
    convert_Aexp_kernel<<<cgrid, 256>>>(x, Aexp);                          // 1
    convert_Wexp_kernel<<<wgrid, wblk>>>(Wq, Wexp + 0ULL * DD * KEXP);     // 2
    convert_Wexp_kernel<<<wgrid, wblk>>>(Wk, Wexp + 1ULL * DD * KEXP);     // 3
    convert_Wexp_kernel<<<wgrid, wblk>>>(Wv, Wexp + 2ULL * DD * KEXP);     // 4

    // fused QKV projection: C = Aexp @ [Wq|Wk|Wv]^T  (N = 3072)
    dim3 qkv_grid(NQKV / GBN, MTOK / GBM);   // (24, 128)
    gemm_mma_kernel<<<qkv_grid, 256, GEMM_SMEM>>>(Aexp, Wexp, bqkv, QKVp, NQKV);  // 5

    attn_kernel<<<MTOK / 2, 128>>>(QKVp, Aexp);                            // 6

    convert_Wexp_kernel<<<wgrid, wblk>>>(Wo, Wexp + 3ULL * DD * KEXP);     // 7

    dim3 o_grid(DD / GBN, MTOK / GBM);       // (8, 128)
    gemm_mma_kernel<<<o_grid, 256, GEMM_SMEM>>>(Aexp, Wexp + 3ULL * DD * KEXP, bo, out, DD);  // 8
}

// round 12
// speedup vs baseline: 2.4673x; 1.5952x over previous
#include <cuda_runtime.h>
#include <cuda_fp16.h>
#include <math.h>
#include <stdint.h>

// Problem shape (fixed)
#define BB 8
#define LL 2048
#define DD 1024
#define NH 16
#define HD 64
#define MTOK (BB * LL)        // 16384 tokens
#define NQKV (3 * DD)         // 3072: fused q|k|v output width

// ======================= scratch ============================================
__device__ float  g_QKV[(size_t)MTOK * NQKV];     // 192 MB (q|k|v per row)
__device__ __half g_Ah[(size_t)MTOK * DD];        // 32 MB fp16 activations
__device__ __half g_Wh[4ULL * DD * DD];           // 8 MB fp16 weights (transposed)
__device__ float  g_bqkv[NQKV];

// ======================= small helpers ======================================
__device__ __forceinline__ uint32_t smem_u32(const void* p) {
    uint32_t a;
    asm("{ .reg .u64 t; cvta.to.shared.u64 t, %1; cvt.u32.u64 %0, t; }"
        : "=r"(a) : "l"(p));
    return a;
}
__device__ __forceinline__ void cp_async16(uint32_t dst, const void* src) {
    asm volatile("cp.async.cg.shared.global [%0], [%1], 16;" :: "r"(dst), "l"(src));
}
#define CP_COMMIT() asm volatile("cp.async.commit_group;" ::: "memory")

__device__ __forceinline__ void ldsm_x4(uint32_t* r, uint32_t addr) {
    asm volatile("ldmatrix.sync.aligned.m8n8.x4.shared.b16 {%0,%1,%2,%3}, [%4];"
                 : "=r"(r[0]), "=r"(r[1]), "=r"(r[2]), "=r"(r[3]) : "r"(addr));
}
__device__ __forceinline__ void mma16816(float* c, const uint32_t* a,
                                         uint32_t b0, uint32_t b1) {
    asm volatile(
        "mma.sync.aligned.m16n8k16.row.col.f32.f16.f16.f32 "
        "{%0,%1,%2,%3}, {%4,%5,%6,%7}, {%8,%9}, {%0,%1,%2,%3};"
        : "+f"(c[0]), "+f"(c[1]), "+f"(c[2]), "+f"(c[3])
        : "r"(a[0]), "r"(a[1]), "r"(a[2]), "r"(a[3]), "r"(b0), "r"(b1));
}

// ======================= conversion kernels =================================
// x [M, DD] fp32 -> fp16 [M, DD]
__global__ void __launch_bounds__(256) convert_Ah_kernel(
    const float* __restrict__ in, __half* __restrict__ out)
{
    int i = blockIdx.x * blockDim.x + threadIdx.x;
    if (i >= MTOK * DD / 4) return;
    float4 v = reinterpret_cast<const float4*>(in)[i];
    __half2 p0 = __halves2half2(__float2half_rn(v.x), __float2half_rn(v.y));
    __half2 p1 = __halves2half2(__float2half_rn(v.z), __float2half_rn(v.w));
    uint2 u;
    u.x = *reinterpret_cast<uint32_t*>(&p0);
    u.y = *reinterpret_cast<uint32_t*>(&p1);
    reinterpret_cast<uint2*>(out)[i] = u;
}

// W [K=DD, N=DD] fp32 -> T [N, DD] fp16 (transposed)
__global__ void __launch_bounds__(256) convert_Wh_kernel(
    const float* __restrict__ W, __half* __restrict__ T)
{
    __shared__ float t[32][33];
    int bx = blockIdx.x * 32, by = blockIdx.y * 32;
    int tx = threadIdx.x, ty = threadIdx.y;
    for (int j = ty; j < 32; j += 8)
        t[j][tx] = W[(size_t)(by + j) * DD + bx + tx];
    __syncthreads();
    for (int j = ty; j < 32; j += 8) {
        float v = t[tx][j];
        T[(size_t)(bx + j) * DD + by + tx] = __float2half_rn(v);
    }
}

__global__ void pack_bias_kernel(const float* __restrict__ bq,
                                 const float* __restrict__ bk,
                                 const float* __restrict__ bv,
                                 float* __restrict__ out)
{
    int i = blockIdx.x * blockDim.x + threadIdx.x;
    if (i >= NQKV) return;
    out[i] = (i < DD) ? bq[i] : (i < 2 * DD) ? bk[i - DD] : bv[i - 2 * DD];
}

// ======================= mma.sync GEMM ======================================
// C[M,N] = A[M,DD] @ B[N,DD]^T + bias
// CTA tile 128x128, 8 warps (4x2), warp tile 32x64, BK=64, 3 stages.
#define GBM 128
#define GBN 128
#define GBK 64
#define GSTAGES 3
#define APAD 8
#define SROW (GBK + APAD)                    // 72 fp16 = 144 B
#define TILE_BYTES (GBM * SROW * 2)          // 18432
#define STAGE_BYTES (2 * TILE_BYTES)         // 36864 (A + B)
#define GEMM_SMEM (GSTAGES * STAGE_BYTES)    // 110592
#define GNIT (DD / GBK)                      // 16

__global__ void __launch_bounds__(256, 2) gemm_mma_kernel(
    const __half* __restrict__ A, const __half* __restrict__ B,
    const float* __restrict__ bias, float* __restrict__ C, int N)
{
    extern __shared__ __half sm[];
    const uint32_t sbase = smem_u32(sm);

    const int tid = threadIdx.x;
    const int lane = tid & 31;
    const int wid = tid >> 5;
    const int wm = wid & 3;          // 0..3 -> 32-row slice
    const int wn = wid >> 2;         // 0..1 -> 64-col slice
    const int bm = blockIdx.y * GBM;
    const int bn = blockIdx.x * GBN;

    float acc[2][8][4];
#pragma unroll
    for (int i = 0; i < 2; i++)
#pragma unroll
        for (int j = 0; j < 8; j++)
#pragma unroll
            for (int q = 0; q < 4; q++) acc[i][j][q] = 0.f;

    // stage loader: A and B each 1024 chunks of 16B, 4 per thread
    auto load_stage = [&](int it, int s) {
        const int kt = it * GBK;
        const uint32_t st = sbase + s * STAGE_BYTES;
#pragma unroll
        for (int i = 0; i < 4; i++) {
            int c = tid + 256 * i;
            int r = c >> 3, ch = c & 7;
            uint32_t off = (r * SROW + ch * 8) * 2;
            cp_async16(st + off,              A + (size_t)(bm + r) * DD + kt + ch * 8);
            cp_async16(st + TILE_BYTES + off, B + (size_t)(bn + r) * DD + kt + ch * 8);
        }
        CP_COMMIT();
    };

    load_stage(0, 0);
    load_stage(1, 1);

    const int a_row = wm * 32 + (lane & 15);
    const int a_kof = ((lane >> 4) & 1) * 8;
    const int b_row = wn * 64 + ((lane >> 4) & 1) * 8 + (lane & 7);
    const int b_kof = ((lane >> 3) & 1) * 8;

    uint32_t af[2][2][4], bf[2][4][4];

    auto load_frags = [&](int buf, uint32_t abase, uint32_t bbase, int k0) {
#pragma unroll
        for (int mi = 0; mi < 2; mi++)
            ldsm_x4(af[buf][mi], abase + ((a_row + mi * 16) * SROW + k0 + a_kof) * 2);
#pragma unroll
        for (int nj = 0; nj < 4; nj++)
            ldsm_x4(bf[buf][nj], bbase + ((b_row + nj * 16) * SROW + k0 + b_kof) * 2);
    };
    auto do_mmas = [&](int buf) {
#pragma unroll
        for (int mi = 0; mi < 2; mi++)
#pragma unroll
            for (int nj = 0; nj < 4; nj++) {
                mma16816(acc[mi][2 * nj],     af[buf][mi], bf[buf][nj][0], bf[buf][nj][1]);
                mma16816(acc[mi][2 * nj + 1], af[buf][mi], bf[buf][nj][2], bf[buf][nj][3]);
            }
    };

    for (int it = 0; it < GNIT; it++) {
        const int s = it % 3;
        asm volatile("cp.async.wait_group 1;" ::: "memory");
        __syncthreads();

        if (it + 2 < GNIT) load_stage(it + 2, (it + 2) % 3);
        else CP_COMMIT();

        const uint32_t abase = sbase + s * STAGE_BYTES;
        const uint32_t bbase = abase + TILE_BYTES;
        // 4 k16 steps, fragments double-buffered so LDSM flies under MMA
        load_frags(0, abase, bbase, 0);
#pragma unroll
        for (int ks = 0; ks < 4; ks++) {
            if (ks < 3) load_frags((ks + 1) & 1, abase, bbase, (ks + 1) * 16);
            do_mmas(ks & 1);
        }
    }

    // epilogue
#pragma unroll
    for (int mi = 0; mi < 2; mi++) {
#pragma unroll
        for (int ni = 0; ni < 8; ni++) {
            int row = bm + wm * 32 + mi * 16 + (lane >> 2);
            int col = bn + wn * 64 + ni * 8 + (lane & 3) * 2;
            float b0 = __ldg(&bias[col]), b1 = __ldg(&bias[col + 1]);
            float2 v0 = {acc[mi][ni][0] + b0, acc[mi][ni][1] + b1};
            float2 v1 = {acc[mi][ni][2] + b0, acc[mi][ni][3] + b1};
            *reinterpret_cast<float2*>(&C[(size_t)row * N + col]) = v0;
            *reinterpret_cast<float2*>(&C[(size_t)(row + 8) * N + col]) = v1;
        }
    }
}

// ======================= per-token attention ================================
// 2 tokens per 128-thread block. QKV row = [q(1024)|k(1024)|v(1024)].
// Output written directly as fp16 into Ah (input of the O projection).
__global__ void __launch_bounds__(128) attn_kernel(
    const float* __restrict__ QKV, __half* __restrict__ Ah)
{
    __shared__ float sk[2][DD];
    __shared__ float sv[2][DD];

    const int tid = threadIdx.x;
    const int sub = tid >> 6;        // token within block
    const int i = tid & 63;          // my HD row
    const int t = blockIdx.x * 2 + sub;
    const float* row = QKV + (size_t)t * NQKV;

#pragma unroll
    for (int h = 0; h < 4; h++) {
        int idx = i + h * 64;
        reinterpret_cast<float4*>(sk[sub])[idx] =
            reinterpret_cast<const float4*>(row + DD)[idx];
        reinterpret_cast<float4*>(sv[sub])[idx] =
            reinterpret_cast<const float4*>(row + 2 * DD)[idx];
    }
    float4 q0 = reinterpret_cast<const float4*>(row)[i * 4 + 0];
    float4 q1 = reinterpret_cast<const float4*>(row)[i * 4 + 1];
    float4 q2 = reinterpret_cast<const float4*>(row)[i * 4 + 2];
    float4 q3 = reinterpret_cast<const float4*>(row)[i * 4 + 3];
    __syncthreads();

    float s[HD];
    float mx = -INFINITY;
#pragma unroll 8
    for (int kk = 0; kk < HD; kk++) {
        float4 k0 = reinterpret_cast<const float4*>(sk[sub])[kk * 4 + 0];
        float4 k1 = reinterpret_cast<const float4*>(sk[sub])[kk * 4 + 1];
        float4 k2 = reinterpret_cast<const float4*>(sk[sub])[kk * 4 + 2];
        float4 k3 = reinterpret_cast<const float4*>(sk[sub])[kk * 4 + 3];
        float dot = q0.x * k0.x + q0.y * k0.y + q0.z * k0.z + q0.w * k0.w
                  + q1.x * k1.x + q1.y * k1.y + q1.z * k1.z + q1.w * k1.w
                  + q2.x * k2.x + q2.y * k2.y + q2.z * k2.z + q2.w * k2.w
                  + q3.x * k3.x + q3.y * k3.y + q3.z * k3.z + q3.w * k3.w;
        float val = dot * 0.25f + 1e-6f;
        bool valid = (kk <= i) && (val != 0.0f);
        s[kk] = valid ? val : -INFINITY;
        if (valid) mx = fmaxf(mx, val);
    }

    float sum = 0.f;
#pragma unroll 8
    for (int kk = 0; kk < HD; kk++) {
        float e = (s[kk] == -INFINITY) ? 0.f : __expf(s[kk] - mx);
        s[kk] = e;
        sum += e;
    }
    float inv = 1.f / sum;

    float4 acc0 = {0, 0, 0, 0}, acc1 = {0, 0, 0, 0};
    float4 acc2 = {0, 0, 0, 0}, acc3 = {0, 0, 0, 0};
#pragma unroll 8
    for (int kk = 0; kk < HD; kk++) {    // uniform: masked probs are exactly 0
        float p = s[kk] * inv;
        float4 v0 = reinterpret_cast<const float4*>(sv[sub])[kk * 4 + 0];
        float4 v1 = reinterpret_cast<const float4*>(sv[sub])[kk * 4 + 1];
        float4 v2 = reinterpret_cast<const float4*>(sv[sub])[kk * 4 + 2];
        float4 v3 = reinterpret_cast<const float4*>(sv[sub])[kk * 4 + 3];
        acc0.x = fmaf(p, v0.x, acc0.x); acc0.y = fmaf(p, v0.y, acc0.y);
        acc0.z = fmaf(p, v0.z, acc0.z); acc0.w = fmaf(p, v0.w, acc0.w);
        acc1.x = fmaf(p, v1.x, acc1.x); acc1.y = fmaf(p, v1.y, acc1.y);
        acc1.z = fmaf(p, v1.z, acc1.z); acc1.w = fmaf(p, v1.w, acc1.w);
        acc2.x = fmaf(p, v2.x, acc2.x); acc2.y = fmaf(p, v2.y, acc2.y);
        acc2.z = fmaf(p, v2.z, acc2.z); acc2.w = fmaf(p, v2.w, acc2.w);
        acc3.x = fmaf(p, v3.x, acc3.x); acc3.y = fmaf(p, v3.y, acc3.y);
        acc3.z = fmaf(p, v3.z, acc3.z); acc3.w = fmaf(p, v3.w, acc3.w);
    }

    // fp16 store
    float a[16] = {acc0.x, acc0.y, acc0.z, acc0.w, acc1.x, acc1.y, acc1.z, acc1.w,
                   acc2.x, acc2.y, acc2.z, acc2.w, acc3.x, acc3.y, acc3.z, acc3.w};
    uint32_t hv[8];
#pragma unroll
    for (int j = 0; j < 8; j++) {
        __half2 ph = __halves2half2(__float2half_rn(a[2 * j]),
                                    __float2half_rn(a[2 * j + 1]));
        hv[j] = *reinterpret_cast<uint32_t*>(&ph);
    }
    __half* ob = Ah + (size_t)t * DD + i * NH;
    uint4* u = reinterpret_cast<uint4*>(hv);
    reinterpret_cast<uint4*>(ob)[0] = u[0];
    reinterpret_cast<uint4*>(ob)[1] = u[1];
}

// ======================= launch =============================================
extern "C" void kernel_launch(void* const* d_in, const int* in_sizes, int n_in,
                              void* d_out, int out_size)
{
    const float* x  = (const float*)d_in[0];
    const float* Wq = (const float*)d_in[1];
    const float* bq = (const float*)d_in[2];
    const float* Wk = (const float*)d_in[3];
    const float* bk = (const float*)d_in[4];
    const float* Wv = (const float*)d_in[5];
    const float* bv = (const float*)d_in[6];
    const float* Wo = (const float*)d_in[7];
    const float* bo = (const float*)d_in[8];
    float* out = (float*)d_out;

    float *QKVp, *bqkv;
    __half *Ah, *Wh;
    cudaGetSymbolAddress((void**)&QKVp, g_QKV);
    cudaGetSymbolAddress((void**)&Ah, g_Ah);
    cudaGetSymbolAddress((void**)&Wh, g_Wh);
    cudaGetSymbolAddress((void**)&bqkv, g_bqkv);

    cudaFuncSetAttribute(gemm_mma_kernel,
                         cudaFuncAttributeMaxDynamicSharedMemorySize, GEMM_SMEM);

    const int n4 = MTOK * DD / 4;
    dim3 cgrid((n4 + 255) / 256);
    dim3 wgrid(DD / 32, DD / 32), wblk(32, 8);

    pack_bias_kernel<<<(NQKV + 255) / 256, 256>>>(bq, bk, bv, bqkv);       // 0
    convert_Ah_kernel<<<cgrid, 256>>>(x, Ah);                              // 1
    convert_Wh_kernel<<<wgrid, wblk>>>(Wq, Wh + 0ULL * DD * DD);           // 2
    convert_Wh_kernel<<<wgrid, wblk>>>(Wk, Wh + 1ULL * DD * DD);           // 3
    convert_Wh_kernel<<<wgrid, wblk>>>(Wv, Wh + 2ULL * DD * DD);           // 4

    // fused QKV projection: C = Ah @ [Wq|Wk|Wv]^T  (N = 3072)
    dim3 qkv_grid(NQKV / GBN, MTOK / GBM);   // (24, 128)
    gemm_mma_kernel<<<qkv_grid, 256, GEMM_SMEM>>>(Ah, Wh, bqkv, QKVp, NQKV);  // 5

    attn_kernel<<<MTOK / 2, 128>>>(QKVp, Ah);                              // 6

    convert_Wh_kernel<<<wgrid, wblk>>>(Wo, Wh + 3ULL * DD * DD);           // 7

    dim3 o_grid(DD / GBN, MTOK / GBM);       // (8, 128)
    gemm_mma_kernel<<<o_grid, 256, GEMM_SMEM>>>(Ah, Wh + 3ULL * DD * DD, bo, out, DD);  // 8
}